// round 3
// baseline (speedup 1.0000x reference)
#include <cuda_runtime.h>
#include <math_constants.h>

// Problem constants (fixed shapes from reference setup_inputs)
#define B 128
#define C 128
#define HW 4096          // 64*64
#define NPLANES (B*C)    // 16384
#define LIFETIME_K 6

// Scratch (no cudaMalloc allowed)
__device__ float g_pooled[NPLANES];
__device__ int   g_pidx[NPLANES];
__device__ float g_life[NPLANES];

// ---------------------------------------------------------------------------
// Kernel 1: per-plane max + first-argmax over 4096 floats.
// One block (256 threads) per plane; each thread loads 4 float4s (coalesced).
// ---------------------------------------------------------------------------
__global__ __launch_bounds__(256) void pool_kernel(const float* __restrict__ in,
                                                   float* __restrict__ pooled,
                                                   int* __restrict__ pidx) {
    const int plane = blockIdx.x;
    const float4* p = reinterpret_cast<const float4*>(in + (size_t)plane * HW);
    const int t = threadIdx.x;

    float best = -CUDART_INF_F;
    int   bi   = 0x7fffffff;

    #pragma unroll
    for (int k = 0; k < 4; k++) {
        const int v4 = t + k * 256;          // float4 index, coalesced across warp
        const float4 v = p[v4];
        const int base = v4 * 4;
        // within-thread indices are strictly increasing -> strict > keeps first max
        if (v.x > best) { best = v.x; bi = base + 0; }
        if (v.y > best) { best = v.y; bi = base + 1; }
        if (v.z > best) { best = v.z; bi = base + 2; }
        if (v.w > best) { best = v.w; bi = base + 3; }
    }

    // warp reduce (value desc, index asc on ties -> first-max semantics)
    #pragma unroll
    for (int o = 16; o; o >>= 1) {
        const float ov = __shfl_down_sync(0xffffffffu, best, o);
        const int   oi = __shfl_down_sync(0xffffffffu, bi,   o);
        if (ov > best || (ov == best && oi < bi)) { best = ov; bi = oi; }
    }

    __shared__ float sv[8];
    __shared__ int   si[8];
    const int warp = t >> 5;
    const int lane = t & 31;
    if (lane == 0) { sv[warp] = best; si[warp] = bi; }
    __syncthreads();

    if (warp == 0) {
        best = (lane < 8) ? sv[lane] : -CUDART_INF_F;
        bi   = (lane < 8) ? si[lane] : 0x7fffffff;
        #pragma unroll
        for (int o = 4; o; o >>= 1) {
            const float ov = __shfl_down_sync(0xffffffffu, best, o);
            const int   oi = __shfl_down_sync(0xffffffffu, bi,   o);
            if (ov > best || (ov == best && oi < bi)) { best = ov; bi = oi; }
        }
        if (lane == 0) { pooled[plane] = best; pidx[plane] = bi; }
    }
}

// ---------------------------------------------------------------------------
// Kernel 2: per-feature top-6 over batch; life = pooled * mask.
// One block per feature c, 128 threads (one per batch b).
// Tie-break: lowest batch index wins (matches jax.lax.top_k stability).
// ---------------------------------------------------------------------------
__global__ __launch_bounds__(B) void topk_kernel(const float* __restrict__ pooled,
                                                 float* __restrict__ life) {
    const int c = blockIdx.x;
    const int b = threadIdx.x;
    const float val = pooled[b * C + c];

    __shared__ float sv[B];
    __shared__ int   si[B];

    float cur = val;
    bool sel = false;

    #pragma unroll
    for (int r = 0; r < LIFETIME_K; r++) {
        sv[b] = cur; si[b] = b;
        __syncthreads();
        #pragma unroll
        for (int o = B / 2; o; o >>= 1) {
            if (b < o) {
                const float ov = sv[b + o];
                const int   oi = si[b + o];
                if (ov > sv[b] || (ov == sv[b] && oi < si[b])) { sv[b] = ov; si[b] = oi; }
            }
            __syncthreads();
        }
        const int winner = si[0];
        __syncthreads();
        if (b == winner) { sel = true; cur = -CUDART_INF_F; }
        __syncthreads();
    }

    life[b * C + c] = sel ? val : 0.0f;
}

// ---------------------------------------------------------------------------
// Kernel 3: fused zero + scatter. Each thread owns one float4 (4 consecutive
// hw positions of one plane); writes zeros unless the plane's argmax lands in
// its chunk AND the lifetime mask kept it (life != 0 encodes that, but we
// write life value directly which is 0 when masked out — identical result).
// ---------------------------------------------------------------------------
__global__ __launch_bounds__(256) void scatter_kernel(const float* __restrict__ life,
                                                      const int* __restrict__ pidx,
                                                      float4* __restrict__ out) {
    const int g = blockIdx.x * blockDim.x + threadIdx.x;   // 16M float4s
    const int e = g << 2;          // element index (fits: 64M < 2^31)
    const int plane = e >> 12;     // /4096
    const int hw = e & (HW - 1);

    float4 r = make_float4(0.f, 0.f, 0.f, 0.f);
    const int ip = pidx[plane];    // L1/L2 broadcast across the 1024 threads of a plane
    const int d = ip - hw;
    if (d >= 0 && d < 4) {
        const float lv = life[plane];
        reinterpret_cast<float*>(&r)[d] = lv;
    }
    out[g] = r;
}

// ---------------------------------------------------------------------------
extern "C" void kernel_launch(void* const* d_in, const int* in_sizes, int n_in,
                              void* d_out, int out_size) {
    const float* act = (const float*)d_in[0];
    float* out = (float*)d_out;

    float* pooled; cudaGetSymbolAddress((void**)&pooled, g_pooled);
    int*   pidx;   cudaGetSymbolAddress((void**)&pidx,   g_pidx);
    float* life;   cudaGetSymbolAddress((void**)&life,   g_life);

    pool_kernel<<<NPLANES, 256>>>(act, pooled, pidx);
    topk_kernel<<<C, B>>>(pooled, life);
    const int n4 = (B * C * HW) / 4;               // 16M float4s
    scatter_kernel<<<n4 / 256, 256>>>(life, pidx, (float4*)out);
}

// round 6
// speedup vs baseline: 1.2112x; 1.2112x over previous
#include <cuda_runtime.h>
#include <math_constants.h>

// Problem constants (fixed shapes from reference setup_inputs)
#define B 128
#define C 128
#define HW 4096          // 64*64
#define NPLANES (B*C)    // 16384
#define LIFETIME_K 6

// Scratch (no cudaMalloc allowed)
__device__ float g_pooled[NPLANES];
__device__ int   g_pidx[NPLANES];

// ---------------------------------------------------------------------------
// Kernel 1: per-plane max + first-argmax over 4096 floats.
// One block (256 threads) per plane; each thread loads 4 float4s (coalesced).
// Measured at 84.6% DRAM / 6.7 TB/s — at the roofline; unchanged.
// ---------------------------------------------------------------------------
__global__ __launch_bounds__(256) void pool_kernel(const float* __restrict__ in,
                                                   float* __restrict__ pooled,
                                                   int* __restrict__ pidx) {
    const int plane = blockIdx.x;
    const float4* p = reinterpret_cast<const float4*>(in + (size_t)plane * HW);
    const int t = threadIdx.x;

    float best = -CUDART_INF_F;
    int   bi   = 0x7fffffff;

    #pragma unroll
    for (int k = 0; k < 4; k++) {
        const int v4 = t + k * 256;          // float4 index, coalesced across warp
        const float4 v = p[v4];
        const int base = v4 * 4;
        // within-thread indices are strictly increasing -> strict > keeps first max
        if (v.x > best) { best = v.x; bi = base + 0; }
        if (v.y > best) { best = v.y; bi = base + 1; }
        if (v.z > best) { best = v.z; bi = base + 2; }
        if (v.w > best) { best = v.w; bi = base + 3; }
    }

    // warp reduce (value desc, index asc on ties -> first-max semantics)
    #pragma unroll
    for (int o = 16; o; o >>= 1) {
        const float ov = __shfl_down_sync(0xffffffffu, best, o);
        const int   oi = __shfl_down_sync(0xffffffffu, bi,   o);
        if (ov > best || (ov == best && oi < bi)) { best = ov; bi = oi; }
    }

    __shared__ float sv[8];
    __shared__ int   si[8];
    const int warp = t >> 5;
    const int lane = t & 31;
    if (lane == 0) { sv[warp] = best; si[warp] = bi; }
    __syncthreads();

    if (warp == 0) {
        best = (lane < 8) ? sv[lane] : -CUDART_INF_F;
        bi   = (lane < 8) ? si[lane] : 0x7fffffff;
        #pragma unroll
        for (int o = 4; o; o >>= 1) {
            const float ov = __shfl_down_sync(0xffffffffu, best, o);
            const int   oi = __shfl_down_sync(0xffffffffu, bi,   o);
            if (ov > best || (ov == best && oi < bi)) { best = ov; bi = oi; }
        }
        if (lane == 0) { pooled[plane] = best; pidx[plane] = bi; }
    }
}

// ---------------------------------------------------------------------------
// Kernel 2: pure zero fill. No loads, no dependencies — pure STG.128 stream.
// 16M float4s; each thread writes 8 float4s (128 B), 8192 blocks x 256 thr.
// ---------------------------------------------------------------------------
__global__ __launch_bounds__(256) void zero_kernel(float4* __restrict__ out) {
    const float4 z = make_float4(0.f, 0.f, 0.f, 0.f);
    // block covers 256*8 = 2048 consecutive float4s
    float4* p = out + (size_t)blockIdx.x * 2048 + threadIdx.x;
    #pragma unroll
    for (int k = 0; k < 8; k++)
        p[k * 256] = z;
}

// ---------------------------------------------------------------------------
// Kernel 3: per-feature top-6 over batch + fused point scatter.
// One block per feature c, 128 threads (one per batch b).
// Tie-break: lowest batch index wins (matches jax.lax.top_k stability).
// After selection, each thread writes its plane's single output element:
// out[plane*HW + pidx[plane]] = life  (life==0 when not selected, which is
// value-identical to the zero background).
// ---------------------------------------------------------------------------
__global__ __launch_bounds__(B) void topk_scatter_kernel(const float* __restrict__ pooled,
                                                         const int* __restrict__ pidx,
                                                         float* __restrict__ out) {
    const int c = blockIdx.x;
    const int b = threadIdx.x;
    const int plane = b * C + c;
    const float val = pooled[plane];

    __shared__ float sv[B];
    __shared__ int   si[B];

    float cur = val;
    bool sel = false;

    #pragma unroll
    for (int r = 0; r < LIFETIME_K; r++) {
        sv[b] = cur; si[b] = b;
        __syncthreads();
        #pragma unroll
        for (int o = B / 2; o; o >>= 1) {
            if (b < o) {
                const float ov = sv[b + o];
                const int   oi = si[b + o];
                if (ov > sv[b] || (ov == sv[b] && oi < si[b])) { sv[b] = ov; si[b] = oi; }
            }
            __syncthreads();
        }
        const int winner = si[0];
        __syncthreads();
        if (b == winner) { sel = true; cur = -CUDART_INF_F; }
        __syncthreads();
    }

    const float life = sel ? val : 0.0f;
    out[(size_t)plane * HW + pidx[plane]] = life;
}

// ---------------------------------------------------------------------------
extern "C" void kernel_launch(void* const* d_in, const int* in_sizes, int n_in,
                              void* d_out, int out_size) {
    const float* act = (const float*)d_in[0];
    float* out = (float*)d_out;

    float* pooled; cudaGetSymbolAddress((void**)&pooled, g_pooled);
    int*   pidx;   cudaGetSymbolAddress((void**)&pidx,   g_pidx);

    pool_kernel<<<NPLANES, 256>>>(act, pooled, pidx);

    const int n4 = (B * C * HW) / 4;               // 16,777,216 float4s
    zero_kernel<<<n4 / 2048, 256>>>((float4*)out); // 8192 blocks

    topk_scatter_kernel<<<C, B>>>(pooled, pidx, out);
}

// round 7
// speedup vs baseline: 1.2818x; 1.0583x over previous
#include <cuda_runtime.h>
#include <math_constants.h>

// Problem constants (fixed shapes from reference setup_inputs)
#define B 128
#define C 128
#define HW 4096          // 64*64
#define NPLANES (B*C)    // 16384
#define LIFETIME_K 6

// Scratch (no cudaMalloc allowed)
__device__ float g_pooled[NPLANES];
__device__ int   g_pidx[NPLANES];

// ---------------------------------------------------------------------------
// Kernel 1 (fused): per-plane zero-fill of the output plane PLUS
// max + first-argmax over the 4096-float input plane.
// The zero stores are independent of the loads — issued first so the store
// stream and load stream overlap in DRAM, turning two serial 256MB passes
// into one 512MB mixed pass.
// One block (256 threads) per plane; 4 float4 stores + 4 float4 loads / thread.
// ---------------------------------------------------------------------------
__global__ __launch_bounds__(256) void pool_zero_kernel(const float* __restrict__ in,
                                                        float4* __restrict__ out4,
                                                        float* __restrict__ pooled,
                                                        int* __restrict__ pidx) {
    const int plane = blockIdx.x;
    const int t = threadIdx.x;

    // ---- independent zero stores for this plane's output (16 KB) ----
    {
        const float4 z = make_float4(0.f, 0.f, 0.f, 0.f);
        float4* o = out4 + (size_t)plane * (HW / 4) + t;
        #pragma unroll
        for (int k = 0; k < 4; k++)
            o[k * 256] = z;
    }

    // ---- input reduction: max + first-argmax ----
    const float4* p = reinterpret_cast<const float4*>(in + (size_t)plane * HW);

    float best = -CUDART_INF_F;
    int   bi   = 0x7fffffff;

    #pragma unroll
    for (int k = 0; k < 4; k++) {
        const int v4 = t + k * 256;          // float4 index, coalesced across warp
        const float4 v = p[v4];
        const int base = v4 * 4;
        // within-thread indices are strictly increasing -> strict > keeps first max
        if (v.x > best) { best = v.x; bi = base + 0; }
        if (v.y > best) { best = v.y; bi = base + 1; }
        if (v.z > best) { best = v.z; bi = base + 2; }
        if (v.w > best) { best = v.w; bi = base + 3; }
    }

    // warp reduce (value desc, index asc on ties -> first-max semantics)
    #pragma unroll
    for (int o = 16; o; o >>= 1) {
        const float ov = __shfl_down_sync(0xffffffffu, best, o);
        const int   oi = __shfl_down_sync(0xffffffffu, bi,   o);
        if (ov > best || (ov == best && oi < bi)) { best = ov; bi = oi; }
    }

    __shared__ float sv[8];
    __shared__ int   si[8];
    const int warp = t >> 5;
    const int lane = t & 31;
    if (lane == 0) { sv[warp] = best; si[warp] = bi; }
    __syncthreads();

    if (warp == 0) {
        best = (lane < 8) ? sv[lane] : -CUDART_INF_F;
        bi   = (lane < 8) ? si[lane] : 0x7fffffff;
        #pragma unroll
        for (int o = 4; o; o >>= 1) {
            const float ov = __shfl_down_sync(0xffffffffu, best, o);
            const int   oi = __shfl_down_sync(0xffffffffu, bi,   o);
            if (ov > best || (ov == best && oi < bi)) { best = ov; bi = oi; }
        }
        if (lane == 0) { pooled[plane] = best; pidx[plane] = bi; }
    }
}

// ---------------------------------------------------------------------------
// Kernel 2: per-feature top-6 over batch + fused point scatter.
// One block per feature c, 128 threads (one per batch b).
// Tie-break: lowest batch index wins (matches jax.lax.top_k stability).
// Each thread then writes its plane's single output element:
// out[plane*HW + pidx[plane]] = life  (life==0 when not selected, which is
// value-identical to the zero background written by kernel 1).
// ---------------------------------------------------------------------------
__global__ __launch_bounds__(B) void topk_scatter_kernel(const float* __restrict__ pooled,
                                                         const int* __restrict__ pidx,
                                                         float* __restrict__ out) {
    const int c = blockIdx.x;
    const int b = threadIdx.x;
    const int plane = b * C + c;
    const float val = pooled[plane];

    __shared__ float sv[B];
    __shared__ int   si[B];

    float cur = val;
    bool sel = false;

    #pragma unroll
    for (int r = 0; r < LIFETIME_K; r++) {
        sv[b] = cur; si[b] = b;
        __syncthreads();
        #pragma unroll
        for (int o = B / 2; o; o >>= 1) {
            if (b < o) {
                const float ov = sv[b + o];
                const int   oi = si[b + o];
                if (ov > sv[b] || (ov == sv[b] && oi < si[b])) { sv[b] = ov; si[b] = oi; }
            }
            __syncthreads();
        }
        const int winner = si[0];
        __syncthreads();
        if (b == winner) { sel = true; cur = -CUDART_INF_F; }
        __syncthreads();
    }

    const float life = sel ? val : 0.0f;
    out[(size_t)plane * HW + pidx[plane]] = life;
}

// ---------------------------------------------------------------------------
extern "C" void kernel_launch(void* const* d_in, const int* in_sizes, int n_in,
                              void* d_out, int out_size) {
    const float* act = (const float*)d_in[0];
    float* out = (float*)d_out;

    float* pooled; cudaGetSymbolAddress((void**)&pooled, g_pooled);
    int*   pidx;   cudaGetSymbolAddress((void**)&pidx,   g_pidx);

    pool_zero_kernel<<<NPLANES, 256>>>(act, (float4*)out, pooled, pidx);
    topk_scatter_kernel<<<C, B>>>(pooled, pidx, out);
}

// round 8
// speedup vs baseline: 1.3489x; 1.0524x over previous
#include <cuda_runtime.h>
#include <math_constants.h>

// Problem constants (fixed shapes from reference setup_inputs)
#define B 128
#define C 128
#define HW 4096          // 64*64
#define NPLANES (B*C)    // 16384
#define LIFETIME_K 6

// Scratch (no cudaMalloc allowed)
__device__ float g_pooledT[NPLANES];   // transposed: [C, B] for coalesced topk loads
__device__ int   g_pidx[NPLANES];      // plane-indexed: [B, C]

// ---------------------------------------------------------------------------
// Kernel 1 (fused): per-plane zero-fill of the output plane PLUS
// max + first-argmax over the 4096-float input plane.
// Zero stores are independent of loads — issued first so the store stream and
// load stream overlap in DRAM (one 512MB mixed pass). Streaming hints keep
// zero-reuse lines from polluting L2.
// One block (256 threads) per plane; 4 float4 stores + 4 float4 loads / thread.
// pooled is written TRANSPOSED ([C,B]) so the topk kernel loads coalesced.
// ---------------------------------------------------------------------------
__global__ __launch_bounds__(256) void pool_zero_kernel(const float* __restrict__ in,
                                                        float4* __restrict__ out4,
                                                        float* __restrict__ pooledT,
                                                        int* __restrict__ pidx) {
    const int plane = blockIdx.x;
    const int t = threadIdx.x;

    // ---- independent zero stores for this plane's output (16 KB) ----
    {
        const float4 z = make_float4(0.f, 0.f, 0.f, 0.f);
        float4* o = out4 + (size_t)plane * (HW / 4) + t;
        #pragma unroll
        for (int k = 0; k < 4; k++)
            __stcs(o + k * 256, z);
    }

    // ---- input reduction: max + first-argmax ----
    const float4* p = reinterpret_cast<const float4*>(in + (size_t)plane * HW);

    float best = -CUDART_INF_F;
    int   bi   = 0x7fffffff;

    #pragma unroll
    for (int k = 0; k < 4; k++) {
        const int v4 = t + k * 256;          // float4 index, coalesced across warp
        const float4 v = __ldcs(p + v4);
        const int base = v4 * 4;
        // within-thread indices are strictly increasing -> strict > keeps first max
        if (v.x > best) { best = v.x; bi = base + 0; }
        if (v.y > best) { best = v.y; bi = base + 1; }
        if (v.z > best) { best = v.z; bi = base + 2; }
        if (v.w > best) { best = v.w; bi = base + 3; }
    }

    // warp reduce (value desc, index asc on ties -> first-max semantics)
    #pragma unroll
    for (int o = 16; o; o >>= 1) {
        const float ov = __shfl_down_sync(0xffffffffu, best, o);
        const int   oi = __shfl_down_sync(0xffffffffu, bi,   o);
        if (ov > best || (ov == best && oi < bi)) { best = ov; bi = oi; }
    }

    __shared__ float sv[8];
    __shared__ int   si[8];
    const int warp = t >> 5;
    const int lane = t & 31;
    if (lane == 0) { sv[warp] = best; si[warp] = bi; }
    __syncthreads();

    if (warp == 0) {
        best = (lane < 8) ? sv[lane] : -CUDART_INF_F;
        bi   = (lane < 8) ? si[lane] : 0x7fffffff;
        #pragma unroll
        for (int o = 4; o; o >>= 1) {
            const float ov = __shfl_down_sync(0xffffffffu, best, o);
            const int   oi = __shfl_down_sync(0xffffffffu, bi,   o);
            if (ov > best || (ov == best && oi < bi)) { best = ov; bi = oi; }
        }
        if (lane == 0) {
            const int c = plane & (C - 1);
            const int b = plane >> 7;        // plane / C
            pooledT[c * B + b] = best;       // transposed store
            pidx[plane] = bi;
        }
    }
}

// ---------------------------------------------------------------------------
// Kernel 2: warp-per-feature top-6 over batch + fused point scatter.
// 32 blocks x 128 threads; warp w of block g handles feature c = g*4+w.
// Each lane holds 4 batch values in registers (coalesced loads from pooledT).
// 6 rounds of register-only argmax via shfl_xor butterfly (value desc,
// batch-index asc on ties — matches jax.lax.top_k stability). No barriers.
// Each lane then writes its 4 planes' single output elements (life==0 for
// non-selected planes is value-identical to the zero background).
// ---------------------------------------------------------------------------
__global__ __launch_bounds__(128) void topk_scatter_kernel(const float* __restrict__ pooledT,
                                                           const int* __restrict__ pidx,
                                                           float* __restrict__ out) {
    const int warp = threadIdx.x >> 5;
    const int lane = threadIdx.x & 31;
    const int c = blockIdx.x * 4 + warp;

    // lane owns batches b = lane, lane+32, lane+64, lane+96 (in-thread b ascending)
    float v[4];
    #pragma unroll
    for (int k = 0; k < 4; k++)
        v[k] = pooledT[c * B + lane + k * 32];

    float cur[4] = {v[0], v[1], v[2], v[3]};
    unsigned selmask = 0;

    #pragma unroll
    for (int r = 0; r < LIFETIME_K; r++) {
        // local argmax: k ascending means b ascending, strict > keeps smallest b
        float lv = cur[0]; int lk = 0;
        #pragma unroll
        for (int k = 1; k < 4; k++)
            if (cur[k] > lv) { lv = cur[k]; lk = k; }
        float bv = lv;
        int   bb = lane + lk * 32;           // global batch index

        // butterfly reduce: max value, tie -> smaller batch index
        #pragma unroll
        for (int o = 16; o; o >>= 1) {
            const float ov = __shfl_xor_sync(0xffffffffu, bv, o);
            const int   ob = __shfl_xor_sync(0xffffffffu, bb, o);
            if (ov > bv || (ov == bv && ob < bb)) { bv = ov; bb = ob; }
        }
        // winner lane retires its value
        if ((bb & 31) == lane) {
            const int k = bb >> 5;
            cur[k] = -CUDART_INF_F;
            selmask |= 1u << k;
        }
    }

    // scatter: each lane writes its 4 planes
    #pragma unroll
    for (int k = 0; k < 4; k++) {
        const int b = lane + k * 32;
        const int plane = b * C + c;
        const float life = ((selmask >> k) & 1u) ? v[k] : 0.0f;
        out[(size_t)plane * HW + pidx[plane]] = life;
    }
}

// ---------------------------------------------------------------------------
extern "C" void kernel_launch(void* const* d_in, const int* in_sizes, int n_in,
                              void* d_out, int out_size) {
    const float* act = (const float*)d_in[0];
    float* out = (float*)d_out;

    float* pooledT; cudaGetSymbolAddress((void**)&pooledT, g_pooledT);
    int*   pidx;    cudaGetSymbolAddress((void**)&pidx,    g_pidx);

    pool_zero_kernel<<<NPLANES, 256>>>(act, (float4*)out, pooledT, pidx);
    topk_scatter_kernel<<<C / 4, 128>>>(pooledT, pidx, out);
}